// round 6
// baseline (speedup 1.0000x reference)
#include <cuda_runtime.h>
#include <cuda_bf16.h>
#include <math.h>

#define BB 1024
#define SS 256
#define DD 128
#define HH 512
#define GG 2048
#define KP2 832          // 128 x_c + 512 hdec + 128 m + 1 d + 63 pad = 13*64
#define NCH 13
#define NIMP (1024*256*128)

#define CHK 64
#define RS 72                        // padded smem row stride (elems)
#define TILE_B (128*RS*2)            // 18432 B per matrix tile
#define BUF_B (4*TILE_B)             // Ah,Al,Bh,Bl
#define GATES_SMEM (2*BUF_B)         // 147456 B double-buffered

typedef unsigned long long ull;
typedef unsigned int uint;

__device__ uint4 g_AhV[BB*KP2/8];
__device__ uint4 g_AlV[BB*KP2/8];
__device__ uint4 g_WhV[(size_t)GG*KP2/8];
__device__ uint4 g_WlV[(size_t)GG*KP2/8];
__device__ float g_h[HH*BB];          // [j][b]
__device__ float g_c[HH*BB];          // [j][b]
__device__ float g_Bc[(HH+DD)*DD];    // [k][n]: rows 0..511 WhrT, 512..639 WfrT
__device__ float g_biasI[GG];         // gcol = 4*j + gate
__device__ float g_loss[SS];
__device__ float g_msum[SS];

#define g_Ah ((__nv_bfloat16*)g_AhV)
#define g_Al ((__nv_bfloat16*)g_AlV)
#define g_Wh ((__nv_bfloat16*)g_WhV)
#define g_Wl ((__nv_bfloat16*)g_WlV)

__device__ __forceinline__ ull pack2(float lo, float hi){
    ull r; asm("mov.b64 %0, {%1,%2};" : "=l"(r) : "f"(lo), "f"(hi)); return r;
}
__device__ __forceinline__ void unpack2(ull v, float &lo, float &hi){
    asm("mov.b64 {%0,%1}, %2;" : "=f"(lo), "=f"(hi) : "l"(v));
}
__device__ __forceinline__ ull ffma2(ull a, ull b, ull c){
    ull d; asm("fma.rn.f32x2 %0, %1, %2, %3;" : "=l"(d) : "l"(a), "l"(b), "l"(c)); return d;
}
__device__ __forceinline__ float sigmoidf_(float x){ return 1.f/(1.f+expf(-x)); }
__device__ __forceinline__ uint smem_u32(const void* p){
    uint a; asm("{ .reg .u64 t; cvta.to.shared.u64 t, %1; cvt.u32.u64 %0, t; }" : "=r"(a) : "l"(p));
    return a;
}
__device__ __forceinline__ void bsplit(float v, __nv_bfloat16 &h, __nv_bfloat16 &l){
    h = __float2bfloat16(v);
    l = __float2bfloat16(v - __bfloat162float(h));
}
__device__ __forceinline__ void cp16(uint dst, const void* src){
    asm volatile("cp.async.cg.shared.global [%0], [%1], 16;" :: "r"(dst), "l"(src));
}
#define CP_COMMIT() asm volatile("cp.async.commit_group;" ::: "memory")
#define CP_WAIT1()  asm volatile("cp.async.wait_group 1;" ::: "memory")
#define CP_WAIT0()  asm volatile("cp.async.wait_group 0;" ::: "memory")

__device__ __forceinline__ void mma16816(float* c, const uint* a, uint b0, uint b1){
    asm volatile("mma.sync.aligned.m16n8k16.row.col.f32.bf16.bf16.f32 "
        "{%0,%1,%2,%3}, {%4,%5,%6,%7}, {%8,%9}, {%0,%1,%2,%3};"
        : "+f"(c[0]), "+f"(c[1]), "+f"(c[2]), "+f"(c[3])
        : "r"(a[0]), "r"(a[1]), "r"(a[2]), "r"(a[3]), "r"(b0), "r"(b1));
}
#define LDM4(r, addr) \
    asm volatile("ldmatrix.sync.aligned.m8n8.x4.shared.b16 {%0,%1,%2,%3}, [%4];" \
        : "=r"((r)[0]), "=r"((r)[1]), "=r"((r)[2]), "=r"((r)[3]) : "r"(addr))

// ---------------- init ----------------
__global__ void init_kernel(const float* __restrict__ data, const float* __restrict__ masks,
                            const float* __restrict__ deltas, const float* __restrict__ bhr){
    int t = blockIdx.x*blockDim.x + threadIdx.x;
    int stride = gridDim.x*blockDim.x;
    for (int idx=t; idx<BB*KP2; idx+=stride){
        int b = idx/KP2, k = idx - b*KP2;
        float v = 0.f;
        if (k < DD){
            float m = masks[(size_t)b*SS*DD + k];
            v = m*data[(size_t)b*SS*DD + k] + (1.f-m)*bhr[k];
        } else if (k >= DD+HH && k < 2*DD+HH){
            v = masks[(size_t)b*SS*DD + (k-DD-HH)];
        } else if (k == 2*DD+HH){
            v = deltas[(size_t)b*SS];
        }
        __nv_bfloat16 h, l; bsplit(v, h, l);
        g_Ah[idx] = h; g_Al[idx] = l;
    }
    for (int i=t;i<HH*BB;i+=stride) g_c[i]=0.f;
    if (t < SS) g_loss[t]=0.f;
}

// ---------------- build packed weights ----------------
__global__ void build_kernel(const float* __restrict__ Wih, const float* __restrict__ Whh,
                             const float* __restrict__ bih, const float* __restrict__ bhh,
                             const float* __restrict__ Whr, const float* __restrict__ Wfr){
    int t0 = blockIdx.x*blockDim.x + threadIdx.x;
    int stride = gridDim.x*blockDim.x;
    const int IN = 2*DD + 1;
    for (size_t idx=t0; idx<(size_t)GG*KP2; idx+=stride){
        int gcol = (int)(idx / KP2);
        int k    = (int)(idx - (size_t)gcol*KP2);
        int j = gcol >> 2, gate = gcol & 3;
        int gs = gate*HH + j;
        float v = 0.f;
        if (k < DD)            v = Wih[(size_t)gs*IN + k];
        else if (k < DD+HH)    v = Whh[(size_t)gs*HH + (k-DD)];
        else if (k < 2*DD+HH)  v = Wih[(size_t)gs*IN + DD + (k-DD-HH)];
        else if (k == 2*DD+HH) v = Wih[(size_t)gs*IN + 2*DD];
        __nv_bfloat16 h, l; bsplit(v, h, l);
        g_Wh[idx] = h; g_Wl[idx] = l;
    }
    for (int gcol=t0; gcol<GG; gcol+=stride){
        int j = gcol>>2, gate = gcol&3; int gs = gate*HH + j;
        g_biasI[gcol] = bih[gs] + bhh[gs];
    }
    for (int idx=t0; idx<(HH+DD)*DD; idx+=stride){
        int k = idx >> 7, n = idx & (DD-1);
        g_Bc[idx] = (k < HH) ? Whr[(size_t)n*HH + k] : Wfr[(size_t)n*DD + (k-HH)];
    }
}

__global__ void msum_kernel(const float* __restrict__ masks){
    __shared__ float red[256];
    int s = blockIdx.x;
    float sum = 0.f;
    for (int idx = threadIdx.x; idx < BB*DD; idx += 256){
        int b = idx >> 7, d = idx & (DD-1);
        sum += masks[(size_t)b*SS*DD + (size_t)s*DD + d];
    }
    red[threadIdx.x] = sum; __syncthreads();
    #pragma unroll
    for (int off=128; off>0; off>>=1){
        if (threadIdx.x < off) red[threadIdx.x] += red[threadIdx.x+off];
        __syncthreads();
    }
    if (threadIdx.x == 0) g_msum[s] = red[0];
}

// ---------------- gates: HMMA bf16 3-split GEMM + fused LSTM (512 thr) ----------------
__device__ __forceinline__ void issue_chunk(uint sb, int buf, int kc,
    const __nv_bfloat16* pAh, const __nv_bfloat16* pAl,
    const __nv_bfloat16* pBh, const __nv_bfloat16* pBl, int tid){
    uint base = sb + buf*BUF_B;
    const __nv_bfloat16* ps[4] = {pAh, pAl, pBh, pBl};
    #pragma unroll
    for (int i = 0; i < 8; i++){
        int lin = i*512 + tid;
        int p = i >> 1;                   // 1024 cp16 per matrix, 2 iters each
        int r = (lin >> 3) & 127;
        int u = lin & 7;
        uint dst = base + p*TILE_B + (uint)(r*RS + u*8)*2;
        cp16(dst, ps[p] + (size_t)r*KP2 + kc + u*8);
    }
}

__global__ __launch_bounds__(512,1) void gates_kernel(){
    extern __shared__ __align__(16) char smem[];
    uint sb = smem_u32(smem);
    int tid = threadIdx.x;
    int w    = tid >> 5;
    int lane = tid & 31;
    int g  = lane >> 2;       // groupID
    int t2 = lane & 3;        // threadID in group
    int wm = w & 3;           // warp M block (rows wm*32)
    int wn = w >> 2;          // warp N block (cols wn*32)
    int row0 = blockIdx.y * 128;
    int col0 = blockIdx.x * 128;

    const __nv_bfloat16* pAh = g_Ah + (size_t)row0*KP2;
    const __nv_bfloat16* pAl = g_Al + (size_t)row0*KP2;
    const __nv_bfloat16* pBh = g_Wh + (size_t)col0*KP2;
    const __nv_bfloat16* pBl = g_Wl + (size_t)col0*KP2;

    // ldmatrix lane base offsets (elems)
    int lrow = lane & 15;
    int lkof = (lane >> 4) << 3;
    uint offA0 = (uint)((wm*32 +      lrow)*RS + lkof);
    uint offA1 = (uint)((wm*32 + 16 + lrow)*RS + lkof);
    uint offB0 = (uint)((wn*32 +      lrow)*RS + lkof);
    uint offB1 = (uint)((wn*32 + 16 + lrow)*RS + lkof);

    float acc[32];
    #pragma unroll
    for (int i = 0; i < 32; i++) acc[i] = 0.f;

    issue_chunk(sb, 0, 0, pAh, pAl, pBh, pBl, tid);
    CP_COMMIT();

    for (int ch = 0; ch < NCH; ch++){
        if (ch < NCH-1){
            issue_chunk(sb, (ch+1)&1, (ch+1)*CHK, pAh, pAl, pBh, pBl, tid);
            CP_COMMIT();
            CP_WAIT1();
        } else {
            CP_WAIT0();
        }
        __syncthreads();

        uint tAh = sb + (ch&1)*BUF_B;
        uint tAl = tAh + TILE_B;
        uint tBh = tAh + 2*TILE_B;
        uint tBl = tAh + 3*TILE_B;

        #pragma unroll
        for (int kk = 0; kk < 4; kk++){
            uint ko = (uint)(kk*16)*2;
            uint ah[2][4], al[2][4], bh[2][4], bl[2][4];
            LDM4(ah[0], tAh + offA0*2 + ko);
            LDM4(ah[1], tAh + offA1*2 + ko);
            LDM4(al[0], tAl + offA0*2 + ko);
            LDM4(al[1], tAl + offA1*2 + ko);
            LDM4(bh[0], tBh + offB0*2 + ko);
            LDM4(bh[1], tBh + offB1*2 + ko);
            LDM4(bl[0], tBl + offB0*2 + ko);
            LDM4(bl[1], tBl + offB1*2 + ko);
            #pragma unroll
            for (int ma = 0; ma < 2; ma++){
                #pragma unroll
                for (int na = 0; na < 4; na++){
                    int nb = na >> 1, hf = na & 1;
                    float* c = &acc[(ma*4 + na)*4];
                    mma16816(c, ah[ma], bh[nb][hf],   bh[nb][hf+2]);
                    mma16816(c, ah[ma], bl[nb][hf],   bl[nb][hf+2]);
                    mma16816(c, al[ma], bh[nb][hf],   bh[nb][hf+2]);
                }
            }
        }
        __syncthreads();
    }

    // fused LSTM epilogue
    #pragma unroll
    for (int ma = 0; ma < 2; ma++){
        #pragma unroll
        for (int na = 0; na < 4; na++){
            float* c = &acc[(ma*4 + na)*4];
            int nb = col0 + wn*32 + na*8;
            int gc = nb + t2*2;
            float2 bi = *(const float2*)&g_biasI[gc];
            c[0] += bi.x; c[1] += bi.y; c[2] += bi.x; c[3] += bi.y;
            float p0 = __shfl_xor_sync(0xFFFFFFFFu, c[0], 1);
            float p1 = __shfl_xor_sync(0xFFFFFFFFu, c[1], 1);
            float p2 = __shfl_xor_sync(0xFFFFFFFFu, c[2], 1);
            float p3 = __shfl_xor_sync(0xFFFFFFFFu, c[3], 1);
            int j = (nb >> 2) + (t2 >> 1);
            int row = wm*32 + ma*16 + g + ((t2 & 1) ? 8 : 0);
            float gi, gf, gg, go;
            if ((t2 & 1) == 0){ gi = c[0]; gf = c[1]; gg = p0; go = p1; }
            else              { gi = p2;   gf = p3;   gg = c[2]; go = c[3]; }
            int b = row0 + row;
            size_t o = (size_t)j*BB + b;
            float cold = g_c[o];
            float cn = sigmoidf_(gf)*cold + sigmoidf_(gi)*tanhf(gg);
            g_c[o] = cn;
            g_h[o] = sigmoidf_(go)*tanhf(cn);
        }
    }
}

// ---------------- mid: stepC(s) + prepA(s+1) fused ----------------
__global__ __launch_bounds__(256,1) void mid_kernel(
    const float* __restrict__ data, const float* __restrict__ masks,
    const float* __restrict__ deltas, const float* __restrict__ Wtd,
    const float* __restrict__ btd, const float* __restrict__ bhr,
    const float* __restrict__ bfr, float* __restrict__ out, int s)
{
    __shared__ float sh_h[8][516];
    __shared__ float sh_hd[8][516];
    __shared__ float sh_x[8][128];
    __shared__ float Bs[16][132];
    __shared__ float red[256];
    __shared__ float sh_d[8];
    int tid = threadIdx.x;
    int m0 = blockIdx.x * 8;
    int tx = tid & 31, ty = tid >> 5;
    bool hasNext = (s+1 < SS);

    if (tid < 8) sh_d[tid] = hasNext ? deltas[(size_t)(m0+tid)*SS + s + 1] : 0.f;
    __syncthreads();

    #pragma unroll 4
    for (int i = 0; i < 16; i++){
        int lin = i*256 + tid;
        int k = lin >> 3, r = lin & 7;
        float hv = g_h[(size_t)k*BB + m0 + r];
        sh_h[r][k] = hv;
        float hd = 0.f;
        if (hasNext){
            float td = sh_d[r]*Wtd[k] + btd[k];
            hd = hv * expf(-fmaxf(td, 0.f));
        }
        sh_hd[r][k] = hd;
    }
    {
        int r = tid >> 5, n4 = (tid & 31) << 2;
        *(float4*)&sh_x[r][n4] = *(const float4*)&data[((size_t)(m0+r)*SS + s)*DD + n4];
    }
    __syncthreads();

    if (hasNext){
        int r = tid >> 5, lw = tid & 31, k0 = lw*16;
        __align__(16) __nv_bfloat16 th[16], tl[16];
        #pragma unroll
        for (int q = 0; q < 16; q++) bsplit(sh_hd[r][k0+q], th[q], tl[q]);
        size_t off = (size_t)(m0+r)*KP2 + DD + k0;
        *(uint4*)(g_Ah+off)   = *(uint4*)th;
        *(uint4*)(g_Ah+off+8) = *(uint4*)(th+8);
        *(uint4*)(g_Al+off)   = *(uint4*)tl;
        *(uint4*)(g_Al+off+8) = *(uint4*)(tl+8);
    }

    ull aH[2]={0,0}, aD[2]={0,0}, aX[2]={0,0};
    for (int k0 = 0; k0 < HH+DD; k0 += 16){
        #pragma unroll
        for (int i = 0; i < 2; i++){
            int lin = i*256 + tid;
            int kk = lin >> 5, n4 = (lin & 31) << 2;
            *(float4*)&Bs[kk][n4] = *(const float4*)&g_Bc[(size_t)(k0+kk)*DD + n4];
        }
        __syncthreads();
        if (k0 < HH){
            #pragma unroll
            for (int kk = 0; kk < 16; kk++){
                float4 bv = *(float4*)&Bs[kk][tx*4];
                ull b0 = pack2(bv.x, bv.y), b1 = pack2(bv.z, bv.w);
                float ah = sh_h[ty][k0+kk];  ull a2 = pack2(ah, ah);
                aH[0] = ffma2(a2, b0, aH[0]); aH[1] = ffma2(a2, b1, aH[1]);
                float ad = sh_hd[ty][k0+kk]; ull d2 = pack2(ad, ad);
                aD[0] = ffma2(d2, b0, aD[0]); aD[1] = ffma2(d2, b1, aD[1]);
            }
        } else {
            #pragma unroll
            for (int kk = 0; kk < 16; kk++){
                float4 bv = *(float4*)&Bs[kk][tx*4];
                float ax = sh_x[ty][k0-HH+kk]; ull a2 = pack2(ax, ax);
                aX[0] = ffma2(a2, pack2(bv.x,bv.y), aX[0]);
                aX[1] = ffma2(a2, pack2(bv.z,bv.w), aX[1]);
            }
        }
        __syncthreads();
    }

    int b = m0 + ty, n0 = tx*4;
    float h2[4], xf[4], hd[4];
    unpack2(aH[0], h2[0], h2[1]); unpack2(aH[1], h2[2], h2[3]);
    unpack2(aX[0], xf[0], xf[1]); unpack2(aX[1], xf[2], xf[3]);
    unpack2(aD[0], hd[0], hd[1]); unpack2(aD[1], hd[2], hd[3]);
    float4 brv = *(const float4*)&bhr[n0];
    float4 frv = *(const float4*)&bfr[n0];
    float4 xv  = *(const float4*)&data [((size_t)b*SS + s)*DD + n0];
    float4 mv  = *(const float4*)&masks[((size_t)b*SS + s)*DD + n0];
    float brr[4]={brv.x,brv.y,brv.z,brv.w}, frr[4]={frv.x,frv.y,frv.z,frv.w};
    float xr[4]={xv.x,xv.y,xv.z,xv.w},      mr[4]={mv.x,mv.y,mv.z,mv.w};
    float lsum = 0.f, ov[4];
    #pragma unroll
    for (int q = 0; q < 4; q++){
        float xh2 = h2[q] + brr[q];
        float xff = xf[q] + frr[q];
        ov[q] = mr[q]*xr[q] + (1.f-mr[q])*(xh2 + xff);
        float e = xr[q] - xh2;
        lsum += e*e*mr[q];
    }
    *(float4*)&out[((size_t)b*SS + s)*DD + n0] = make_float4(ov[0], ov[1], ov[2], ov[3]);

    if (hasNext){
        float4 xn = *(const float4*)&data [((size_t)b*SS + s+1)*DD + n0];
        float4 mn = *(const float4*)&masks[((size_t)b*SS + s+1)*DD + n0];
        float xnr[4]={xn.x,xn.y,xn.z,xn.w}, mnr[4]={mn.x,mn.y,mn.z,mn.w};
        __align__(8) __nv_bfloat16 ah4[4], al4[4], mh4[4], ml4[4];
        #pragma unroll
        for (int q = 0; q < 4; q++){
            float xh = hd[q] + brr[q];
            float xc = mnr[q]*xnr[q] + (1.f-mnr[q])*xh;
            bsplit(xc, ah4[q], al4[q]);
            bsplit(mnr[q], mh4[q], ml4[q]);
        }
        size_t ob = (size_t)b*KP2 + n0;
        *(uint2*)(g_Ah + ob) = *(uint2*)ah4;
        *(uint2*)(g_Al + ob) = *(uint2*)al4;
        size_t om = (size_t)b*KP2 + DD + HH + n0;
        *(uint2*)(g_Ah + om) = *(uint2*)mh4;
        *(uint2*)(g_Al + om) = *(uint2*)ml4;
        if (tx == 0){
            __nv_bfloat16 dh, dl; bsplit(sh_d[ty], dh, dl);
            g_Ah[(size_t)b*KP2 + 2*DD + HH] = dh;
            g_Al[(size_t)b*KP2 + 2*DD + HH] = dl;
        }
    }

    red[tid] = lsum; __syncthreads();
    #pragma unroll
    for (int off = 128; off > 0; off >>= 1){
        if (tid < off) red[tid] += red[tid+off];
        __syncthreads();
    }
    if (tid == 0) atomicAdd(&g_loss[s], red[0]);
}

__global__ void final_kernel(float* __restrict__ out, int out_size){
    __shared__ float red[256];
    int s = threadIdx.x;
    red[s] = g_loss[s] / (g_msum[s] + 1e-5f);
    __syncthreads();
    #pragma unroll
    for (int off = 128; off > 0; off >>= 1){
        if (s < off) red[s] += red[s+off];
        __syncthreads();
    }
    if (s == 0 && out_size > NIMP) out[NIMP] = red[0] / (float)SS;
}

extern "C" void kernel_launch(void* const* d_in, const int* in_sizes, int n_in,
                              void* d_out, int out_size){
    const float* data   = (const float*)d_in[0];
    const float* masks  = (const float*)d_in[1];
    const float* deltas = (const float*)d_in[2];
    const float* Wih    = (const float*)d_in[3];
    const float* Whh    = (const float*)d_in[4];
    const float* bih    = (const float*)d_in[5];
    const float* bhh    = (const float*)d_in[6];
    const float* Wtd    = (const float*)d_in[7];
    const float* btd    = (const float*)d_in[8];
    const float* Whr    = (const float*)d_in[9];
    const float* bhr    = (const float*)d_in[10];
    const float* Wfr    = (const float*)d_in[11];
    const float* bfr    = (const float*)d_in[12];
    float* out = (float*)d_out;

    cudaFuncSetAttribute(gates_kernel, cudaFuncAttributeMaxDynamicSharedMemorySize, GATES_SMEM);

    init_kernel<<<512, 256>>>(data, masks, deltas, bhr);
    build_kernel<<<512, 256>>>(Wih, Whh, bih, bhh, Whr, Wfr);
    msum_kernel<<<SS, 256>>>(masks);
    for (int s = 0; s < SS; s++){
        gates_kernel<<<dim3(16, 8), 512, GATES_SMEM>>>();
        mid_kernel<<<BB/8, 256>>>(data, masks, deltas, Wtd, btd, bhr, bfr, out, s);
    }
    final_kernel<<<1, 256>>>(out, out_size);
}

// round 8
// speedup vs baseline: 1.1114x; 1.1114x over previous
#include <cuda_runtime.h>
#include <cuda_bf16.h>
#include <math.h>

#define BB 1024
#define SS 256
#define DD 128
#define HH 512
#define GG 2048
#define KP2 832          // 13 chunks of 64
#define NCH 13
#define NIMP (1024*256*128)

#define TILE16K 16384
#define BUF_B (4*TILE16K)            // Ah,Al,Bh,Bl tiles
#define GATES_SMEM (2*BUF_B + 32)    // double buffer + 2 mbarriers

typedef unsigned long long ull;
typedef unsigned int uint;

// chunk-major, pre-swizzled: A [ch][b][8 units][8], W [ch][gcol][8 units][8]
__device__ uint4 g_AhV[BB*KP2/8];
__device__ uint4 g_AlV[BB*KP2/8];
__device__ uint4 g_WhV[(size_t)GG*KP2/8];
__device__ uint4 g_WlV[(size_t)GG*KP2/8];
__device__ float g_h[HH*BB];          // [j][b]
__device__ float g_c[HH*BB];          // [j][b]
__device__ float g_Bc[(HH+DD)*DD];    // [k][n]: rows 0..511 WhrT, 512..639 WfrT
__device__ float g_biasI[GG];         // gcol = 4*j + gate
__device__ float g_loss[SS];
__device__ float g_msum[SS];

#define g_Ah ((__nv_bfloat16*)g_AhV)
#define g_Al ((__nv_bfloat16*)g_AlV)
#define g_Wh ((__nv_bfloat16*)g_WhV)
#define g_Wl ((__nv_bfloat16*)g_WlV)

__device__ __forceinline__ size_t aoff(int b, int k){
    int ch = k >> 6;
    int u  = ((k >> 3) & 7) ^ (b & 7);
    return (((size_t)ch*BB + b)*8 + u)*8 + (k & 7);
}
__device__ __forceinline__ size_t woff(int g, int k){
    int ch = k >> 6;
    int u  = ((k >> 3) & 7) ^ (g & 7);
    return (((size_t)ch*GG + g)*8 + u)*8 + (k & 7);
}

__device__ __forceinline__ ull pack2(float lo, float hi){
    ull r; asm("mov.b64 %0, {%1,%2};" : "=l"(r) : "f"(lo), "f"(hi)); return r;
}
__device__ __forceinline__ void unpack2(ull v, float &lo, float &hi){
    asm("mov.b64 {%0,%1}, %2;" : "=f"(lo), "=f"(hi) : "l"(v));
}
__device__ __forceinline__ ull ffma2(ull a, ull b, ull c){
    ull d; asm("fma.rn.f32x2 %0, %1, %2, %3;" : "=l"(d) : "l"(a), "l"(b), "l"(c)); return d;
}
__device__ __forceinline__ float sigmoidf_(float x){ return 1.f/(1.f+expf(-x)); }
__device__ __forceinline__ uint smem_u32(const void* p){
    uint a; asm("{ .reg .u64 t; cvta.to.shared.u64 t, %1; cvt.u32.u64 %0, t; }" : "=r"(a) : "l"(p));
    return a;
}
__device__ __forceinline__ void bsplit(float v, __nv_bfloat16 &h, __nv_bfloat16 &l){
    h = __float2bfloat16(v);
    l = __float2bfloat16(v - __bfloat162float(h));
}

#define MBAR_INIT(a) asm volatile("mbarrier.init.shared.b64 [%0], %1;" :: "r"(a), "r"(1u) : "memory")
#define MBAR_EXPECT(a, bytes) asm volatile("mbarrier.arrive.expect_tx.shared.b64 _, [%0], %1;" :: "r"(a), "r"(bytes) : "memory")
#define WAITP(a, par) do{ \
    asm volatile("{\n\t.reg .pred P;\n\tWL_%=:\n\t" \
      "mbarrier.try_wait.parity.acquire.cta.shared::cta.b64 P, [%0], %1, 0x989680;\n\t" \
      "@P bra.uni WD_%=;\n\tbra.uni WL_%=;\n\tWD_%=:\n\t}" \
      :: "r"(a), "r"(par) : "memory"); }while(0)
#define BULK_G2S(dst, src, bytes, mbar) \
    asm volatile("cp.async.bulk.shared::cluster.global.mbarrier::complete_tx::bytes [%0], [%1], %2, [%3];" \
        :: "r"(dst), "l"(src), "r"(bytes), "r"(mbar) : "memory")

__device__ __forceinline__ void mma16816(float* c, const uint* a, uint b0, uint b1){
    asm volatile("mma.sync.aligned.m16n8k16.row.col.f32.bf16.bf16.f32 "
        "{%0,%1,%2,%3}, {%4,%5,%6,%7}, {%8,%9}, {%0,%1,%2,%3};"
        : "+f"(c[0]), "+f"(c[1]), "+f"(c[2]), "+f"(c[3])
        : "r"(a[0]), "r"(a[1]), "r"(a[2]), "r"(a[3]), "r"(b0), "r"(b1));
}
#define LDM4(r, addr) \
    asm volatile("ldmatrix.sync.aligned.m8n8.x4.shared.b16 {%0,%1,%2,%3}, [%4];" \
        : "=r"((r)[0]), "=r"((r)[1]), "=r"((r)[2]), "=r"((r)[3]) : "r"(addr))

// ---------------- init ----------------
__global__ void init_kernel(const float* __restrict__ data, const float* __restrict__ masks,
                            const float* __restrict__ deltas, const float* __restrict__ bhr){
    int t = blockIdx.x*blockDim.x + threadIdx.x;
    int stride = gridDim.x*blockDim.x;
    for (int idx=t; idx<BB*KP2; idx+=stride){
        int b = idx/KP2, k = idx - b*KP2;
        float v = 0.f;
        if (k < DD){
            float m = masks[(size_t)b*SS*DD + k];
            v = m*data[(size_t)b*SS*DD + k] + (1.f-m)*bhr[k];
        } else if (k >= DD+HH && k < 2*DD+HH){
            v = masks[(size_t)b*SS*DD + (k-DD-HH)];
        } else if (k == 2*DD+HH){
            v = deltas[(size_t)b*SS];
        }
        __nv_bfloat16 h, l; bsplit(v, h, l);
        size_t o = aoff(b, k);
        g_Ah[o] = h; g_Al[o] = l;
    }
    for (int i=t;i<HH*BB;i+=stride) g_c[i]=0.f;
    if (t < SS) g_loss[t]=0.f;
}

// ---------------- build packed weights ----------------
__global__ void build_kernel(const float* __restrict__ Wih, const float* __restrict__ Whh,
                             const float* __restrict__ bih, const float* __restrict__ bhh,
                             const float* __restrict__ Whr, const float* __restrict__ Wfr){
    int t0 = blockIdx.x*blockDim.x + threadIdx.x;
    int stride = gridDim.x*blockDim.x;
    const int IN = 2*DD + 1;
    for (size_t idx=t0; idx<(size_t)GG*KP2; idx+=stride){
        int gcol = (int)(idx / KP2);
        int k    = (int)(idx - (size_t)gcol*KP2);
        int j = gcol >> 2, gate = gcol & 3;
        int gs = gate*HH + j;
        float v = 0.f;
        if (k < DD)            v = Wih[(size_t)gs*IN + k];
        else if (k < DD+HH)    v = Whh[(size_t)gs*HH + (k-DD)];
        else if (k < 2*DD+HH)  v = Wih[(size_t)gs*IN + DD + (k-DD-HH)];
        else if (k == 2*DD+HH) v = Wih[(size_t)gs*IN + 2*DD];
        __nv_bfloat16 h, l; bsplit(v, h, l);
        size_t o = woff(gcol, k);
        g_Wh[o] = h; g_Wl[o] = l;
    }
    for (int gcol=t0; gcol<GG; gcol+=stride){
        int j = gcol>>2, gate = gcol&3; int gs = gate*HH + j;
        g_biasI[gcol] = bih[gs] + bhh[gs];
    }
    for (int idx=t0; idx<(HH+DD)*DD; idx+=stride){
        int k = idx >> 7, n = idx & (DD-1);
        g_Bc[idx] = (k < HH) ? Whr[(size_t)n*HH + k] : Wfr[(size_t)n*DD + (k-HH)];
    }
}

__global__ void msum_kernel(const float* __restrict__ masks){
    __shared__ float red[256];
    int s = blockIdx.x;
    float sum = 0.f;
    for (int idx = threadIdx.x; idx < BB*DD; idx += 256){
        int b = idx >> 7, d = idx & (DD-1);
        sum += masks[(size_t)b*SS*DD + (size_t)s*DD + d];
    }
    red[threadIdx.x] = sum; __syncthreads();
    #pragma unroll
    for (int off=128; off>0; off>>=1){
        if (threadIdx.x < off) red[threadIdx.x] += red[threadIdx.x+off];
        __syncthreads();
    }
    if (threadIdx.x == 0) g_msum[s] = red[0];
}

// ---------------- gates: HMMA + bulk-copy pipeline (512 thr) ----------------
__global__ __launch_bounds__(512,1) void gates_kernel(){
    extern __shared__ __align__(16) char smem[];
    uint sb = smem_u32(smem);
    uint mb0 = sb + 2*BUF_B;
    uint mb1 = mb0 + 8;
    int tid = threadIdx.x;
    int w    = tid >> 5;
    int lane = tid & 31;
    int g  = lane >> 2;
    int t2 = lane & 3;
    int wm = w & 3;           // rows wm*32
    int wn = w >> 2;          // cols wn*32
    int row0 = blockIdx.y * 128;
    int col0 = blockIdx.x * 128;

    if (tid == 0){ MBAR_INIT(mb0); MBAR_INIT(mb1); }
    __syncthreads();

    // ldmatrix per-lane bases (swizzled layout: row*128 + (unit^(row&7))*16)
    int lrow = lane & 15;
    int hi   = lane >> 4;
    int sw7  = lrow & 7;
    uint baseA0 = (uint)((wm*32 +      lrow)*128);
    uint baseA1 = (uint)((wm*32 + 16 + lrow)*128);
    uint baseB0 = (uint)((wn*32 +      lrow)*128);
    uint baseB1 = (uint)((wn*32 + 16 + lrow)*128);

    float acc[32];
    #pragma unroll
    for (int i = 0; i < 32; i++) acc[i] = 0.f;

    // prologue: load chunk 0 into buf 0
    if (tid == 0){
        MBAR_EXPECT(mb0, 4*TILE16K);
        BULK_G2S(sb + 0*TILE16K, g_Ah + ((size_t)0*BB + row0)*64, TILE16K, mb0);
        BULK_G2S(sb + 1*TILE16K, g_Al + ((size_t)0*BB + row0)*64, TILE16K, mb0);
        BULK_G2S(sb + 2*TILE16K, g_Wh + ((size_t)0*GG + col0)*64, TILE16K, mb0);
        BULK_G2S(sb + 3*TILE16K, g_Wl + ((size_t)0*GG + col0)*64, TILE16K, mb0);
    }

    uint ph0 = 0, ph1 = 0;
    for (int ch = 0; ch < NCH; ch++){
        int buf = ch & 1;
        uint mb = buf ? mb1 : mb0;
        if (buf){ WAITP(mb, ph1); ph1 ^= 1; }
        else    { WAITP(mb, ph0); ph0 ^= 1; }

        if (tid == 0 && ch+1 < NCH){
            int nb = (ch+1) & 1;
            uint mbn = nb ? mb1 : mb0;
            uint db = sb + nb*BUF_B;
            size_t kcA = ((size_t)(ch+1)*BB + row0)*64;
            size_t kcW = ((size_t)(ch+1)*GG + col0)*64;
            MBAR_EXPECT(mbn, 4*TILE16K);
            BULK_G2S(db + 0*TILE16K, g_Ah + kcA, TILE16K, mbn);
            BULK_G2S(db + 1*TILE16K, g_Al + kcA, TILE16K, mbn);
            BULK_G2S(db + 2*TILE16K, g_Wh + kcW, TILE16K, mbn);
            BULK_G2S(db + 3*TILE16K, g_Wl + kcW, TILE16K, mbn);
        }

        uint tAh = sb + buf*BUF_B;
        uint tAl = tAh + TILE16K;
        uint tBh = tAh + 2*TILE16K;
        uint tBl = tAh + 3*TILE16K;

        #pragma unroll
        for (int kk = 0; kk < 4; kk++){
            uint off = (uint)(((((kk<<1)|hi) ^ sw7)) << 4);
            uint ah[2][4], al[2][4], bh[2][4], bl[2][4];
            LDM4(ah[0], tAh + baseA0 + off);
            LDM4(ah[1], tAh + baseA1 + off);
            LDM4(al[0], tAl + baseA0 + off);
            LDM4(al[1], tAl + baseA1 + off);
            LDM4(bh[0], tBh + baseB0 + off);
            LDM4(bh[1], tBh + baseB1 + off);
            LDM4(bl[0], tBl + baseB0 + off);
            LDM4(bl[1], tBl + baseB1 + off);
            #pragma unroll
            for (int ma = 0; ma < 2; ma++){
                #pragma unroll
                for (int na = 0; na < 4; na++){
                    int nb = na >> 1, hf = na & 1;
                    float* c = &acc[(ma*4 + na)*4];
                    mma16816(c, ah[ma], bh[nb][hf], bh[nb][hf+2]);
                    mma16816(c, ah[ma], bl[nb][hf], bl[nb][hf+2]);
                    mma16816(c, al[ma], bh[nb][hf], bh[nb][hf+2]);
                }
            }
        }
        __syncthreads();
    }

    // fused LSTM epilogue
    #pragma unroll
    for (int ma = 0; ma < 2; ma++){
        #pragma unroll
        for (int na = 0; na < 4; na++){
            float* c = &acc[(ma*4 + na)*4];
            int nb = col0 + wn*32 + na*8;
            int gc = nb + t2*2;
            float2 bi = *(const float2*)&g_biasI[gc];
            c[0] += bi.x; c[1] += bi.y; c[2] += bi.x; c[3] += bi.y;
            float p0 = __shfl_xor_sync(0xFFFFFFFFu, c[0], 1);
            float p1 = __shfl_xor_sync(0xFFFFFFFFu, c[1], 1);
            float p2 = __shfl_xor_sync(0xFFFFFFFFu, c[2], 1);
            float p3 = __shfl_xor_sync(0xFFFFFFFFu, c[3], 1);
            int j = (nb >> 2) + (t2 >> 1);
            int row = wm*32 + ma*16 + g + ((t2 & 1) ? 8 : 0);
            float gi, gf, gg, go;
            if ((t2 & 1) == 0){ gi = c[0]; gf = c[1]; gg = p0; go = p1; }
            else              { gi = p2;   gf = p3;   gg = c[2]; go = c[3]; }
            int b = row0 + row;
            size_t o = (size_t)j*BB + b;
            float cold = g_c[o];
            float cn = sigmoidf_(gf)*cold + sigmoidf_(gi)*tanhf(gg);
            g_c[o] = cn;
            g_h[o] = sigmoidf_(go)*tanhf(cn);
        }
    }
}

// ---------------- mid: stepC(s) + prepA(s+1) fused ----------------
__global__ __launch_bounds__(256,1) void mid_kernel(
    const float* __restrict__ data, const float* __restrict__ masks,
    const float* __restrict__ deltas, const float* __restrict__ Wtd,
    const float* __restrict__ btd, const float* __restrict__ bhr,
    const float* __restrict__ bfr, float* __restrict__ out, int s)
{
    __shared__ float sh_h[8][516];
    __shared__ float sh_hd[8][516];
    __shared__ float sh_x[8][128];
    __shared__ float Bs[16][132];
    __shared__ float red[256];
    __shared__ float sh_d[8];
    int tid = threadIdx.x;
    int m0 = blockIdx.x * 8;
    int tx = tid & 31, ty = tid >> 5;
    bool hasNext = (s+1 < SS);

    if (tid < 8) sh_d[tid] = hasNext ? deltas[(size_t)(m0+tid)*SS + s + 1] : 0.f;
    __syncthreads();

    #pragma unroll 4
    for (int i = 0; i < 16; i++){
        int lin = i*256 + tid;
        int k = lin >> 3, r = lin & 7;
        float hv = g_h[(size_t)k*BB + m0 + r];
        sh_h[r][k] = hv;
        float hd = 0.f;
        if (hasNext){
            float td = sh_d[r]*Wtd[k] + btd[k];
            hd = hv * expf(-fmaxf(td, 0.f));
        }
        sh_hd[r][k] = hd;
    }
    {
        int r = tid >> 5, n4 = (tid & 31) << 2;
        *(float4*)&sh_x[r][n4] = *(const float4*)&data[((size_t)(m0+r)*SS + s)*DD + n4];
    }
    __syncthreads();

    // write hdec region of A(s+1): k = 128 + lw*16 + [0..15]
    if (hasNext){
        int r = tid >> 5, lw = tid & 31;
        int b = m0 + r;
        __align__(16) __nv_bfloat16 th[16], tl[16];
        #pragma unroll
        for (int q = 0; q < 16; q++) bsplit(sh_hd[r][lw*16+q], th[q], tl[q]);
        #pragma unroll
        for (int h2 = 0; h2 < 2; h2++){
            int ug = 16 + lw*2 + h2;                // global 8-elem unit index
            int ch = ug >> 3, u = (ug & 7) ^ (b & 7);
            size_t o = (((size_t)ch*BB + b)*8 + u)*8;
            *(uint4*)(g_Ah + o) = *(uint4*)(th + h2*8);
            *(uint4*)(g_Al + o) = *(uint4*)(tl + h2*8);
        }
    }

    ull aH[2]={0,0}, aD[2]={0,0}, aX[2]={0,0};
    for (int k0 = 0; k0 < HH+DD; k0 += 16){
        #pragma unroll
        for (int i = 0; i < 2; i++){
            int lin = i*256 + tid;
            int kk = lin >> 5, n4 = (lin & 31) << 2;
            *(float4*)&Bs[kk][n4] = *(const float4*)&g_Bc[(size_t)(k0+kk)*DD + n4];
        }
        __syncthreads();
        if (k0 < HH){
            #pragma unroll
            for (int kk = 0; kk < 16; kk++){
                float4 bv = *(float4*)&Bs[kk][tx*4];
                ull b0 = pack2(bv.x, bv.y), b1 = pack2(bv.z, bv.w);
                float ah = sh_h[ty][k0+kk];  ull a2 = pack2(ah, ah);
                aH[0] = ffma2(a2, b0, aH[0]); aH[1] = ffma2(a2, b1, aH[1]);
                float ad = sh_hd[ty][k0+kk]; ull d2 = pack2(ad, ad);
                aD[0] = ffma2(d2, b0, aD[0]); aD[1] = ffma2(d2, b1, aD[1]);
            }
        } else {
            #pragma unroll
            for (int kk = 0; kk < 16; kk++){
                float4 bv = *(float4*)&Bs[kk][tx*4];
                float ax = sh_x[ty][k0-HH+kk]; ull a2 = pack2(ax, ax);
                aX[0] = ffma2(a2, pack2(bv.x,bv.y), aX[0]);
                aX[1] = ffma2(a2, pack2(bv.z,bv.w), aX[1]);
            }
        }
        __syncthreads();
    }

    int b = m0 + ty, n0 = tx*4;
    float h2v[4], xf[4], hd[4];
    unpack2(aH[0], h2v[0], h2v[1]); unpack2(aH[1], h2v[2], h2v[3]);
    unpack2(aX[0], xf[0], xf[1]);  unpack2(aX[1], xf[2], xf[3]);
    unpack2(aD[0], hd[0], hd[1]);  unpack2(aD[1], hd[2], hd[3]);
    float4 brv = *(const float4*)&bhr[n0];
    float4 frv = *(const float4*)&bfr[n0];
    float4 xv  = *(const float4*)&data [((size_t)b*SS + s)*DD + n0];
    float4 mv  = *(const float4*)&masks[((size_t)b*SS + s)*DD + n0];
    float brr[4]={brv.x,brv.y,brv.z,brv.w}, frr[4]={frv.x,frv.y,frv.z,frv.w};
    float xr[4]={xv.x,xv.y,xv.z,xv.w},      mr[4]={mv.x,mv.y,mv.z,mv.w};
    float lsum = 0.f, ov[4];
    #pragma unroll
    for (int q = 0; q < 4; q++){
        float xh2 = h2v[q] + brr[q];
        float xff = xf[q] + frr[q];
        ov[q] = mr[q]*xr[q] + (1.f-mr[q])*(xh2 + xff);
        float e = xr[q] - xh2;
        lsum += e*e*mr[q];
    }
    *(float4*)&out[((size_t)b*SS + s)*DD + n0] = make_float4(ov[0], ov[1], ov[2], ov[3]);

    if (hasNext){
        float4 xn = *(const float4*)&data [((size_t)b*SS + s+1)*DD + n0];
        float4 mn = *(const float4*)&masks[((size_t)b*SS + s+1)*DD + n0];
        float xnr[4]={xn.x,xn.y,xn.z,xn.w}, mnr[4]={mn.x,mn.y,mn.z,mn.w};
        __align__(8) __nv_bfloat16 ah4[4], al4[4], mh4[4], ml4[4];
        #pragma unroll
        for (int q = 0; q < 4; q++){
            float xh = hd[q] + brr[q];
            float xc = mnr[q]*xnr[q] + (1.f-mnr[q])*xh;
            bsplit(xc, ah4[q], al4[q]);
            bsplit(mnr[q], mh4[q], ml4[q]);
        }
        // x_c: k = n0..n0+3  (unit ug = n0>>3, elem offset n0&7 in {0,4})
        {
            int ug = n0 >> 3;
            int ch = ug >> 3, u = (ug & 7) ^ (b & 7);
            size_t o = (((size_t)ch*BB + b)*8 + u)*8 + (n0 & 7);
            *(uint2*)(g_Ah + o) = *(uint2*)ah4;
            *(uint2*)(g_Al + o) = *(uint2*)al4;
        }
        // m: k = 640 + n0
        {
            int ug = 80 + (n0 >> 3);
            int ch = ug >> 3, u = (ug & 7) ^ (b & 7);
            size_t o = (((size_t)ch*BB + b)*8 + u)*8 + (n0 & 7);
            *(uint2*)(g_Ah + o) = *(uint2*)mh4;
            *(uint2*)(g_Al + o) = *(uint2*)ml4;
        }
        if (tx == 0){
            __nv_bfloat16 dh, dl; bsplit(sh_d[ty], dh, dl);
            size_t o = (((size_t)12*BB + b)*8 + (b & 7))*8;   // k=768: ug=96, u=0^(b&7)
            g_Ah[o] = dh;
            g_Al[o] = dl;
        }
    }

    red[tid] = lsum; __syncthreads();
    #pragma unroll
    for (int off = 128; off > 0; off >>= 1){
        if (tid < off) red[tid] += red[tid+off];
        __syncthreads();
    }
    if (tid == 0) atomicAdd(&g_loss[s], red[0]);
}

__global__ void final_kernel(float* __restrict__ out, int out_size){
    __shared__ float red[256];
    int s = threadIdx.x;
    red[s] = g_loss[s] / (g_msum[s] + 1e-5f);
    __syncthreads();
    #pragma unroll
    for (int off = 128; off > 0; off >>= 1){
        if (s < off) red[s] += red[s+off];
        __syncthreads();
    }
    if (s == 0 && out_size > NIMP) out[NIMP] = red[0] / (float)SS;
}

extern "C" void kernel_launch(void* const* d_in, const int* in_sizes, int n_in,
                              void* d_out, int out_size){
    const float* data   = (const float*)d_in[0];
    const float* masks  = (const float*)d_in[1];
    const float* deltas = (const float*)d_in[2];
    const float* Wih    = (const float*)d_in[3];
    const float* Whh    = (const float*)d_in[4];
    const float* bih    = (const float*)d_in[5];
    const float* bhh    = (const float*)d_in[6];
    const float* Wtd    = (const float*)d_in[7];
    const float* btd    = (const float*)d_in[8];
    const float* Whr    = (const float*)d_in[9];
    const float* bhr    = (const float*)d_in[10];
    const float* Wfr    = (const float*)d_in[11];
    const float* bfr    = (const float*)d_in[12];
    float* out = (float*)d_out;

    cudaFuncSetAttribute(gates_kernel, cudaFuncAttributeMaxDynamicSharedMemorySize, GATES_SMEM);

    init_kernel<<<512, 256>>>(data, masks, deltas, bhr);
    build_kernel<<<512, 256>>>(Wih, Whh, bih, bhh, Whr, Wfr);
    msum_kernel<<<SS, 256>>>(masks);
    for (int s = 0; s < SS; s++){
        gates_kernel<<<dim3(16, 8), 512, GATES_SMEM>>>();
        mid_kernel<<<BB/8, 256>>>(data, masks, deltas, Wtd, btd, bhr, bfr, out, s);
    }
    final_kernel<<<1, 256>>>(out, out_size);
}

// round 10
// speedup vs baseline: 1.2225x; 1.1000x over previous
#include <cuda_runtime.h>
#include <cuda_bf16.h>
#include <math.h>

#define BB 1024
#define SS 256
#define DD 128
#define HH 512
#define GG 2048
#define KP2 832          // 13 chunks of 64
#define NCH 13
#define NIMP (1024*256*128)

#define TILE16K 16384
#define BUF_B (4*TILE16K)
#define GATES_SMEM (2*BUF_B + 32)

// mid dynamic smem layout (floats)
#define MID_H    0                       // sh_h  [8][516]
#define MID_HD   (8*516)                 // sh_hd [8][516]
#define MID_X    (2*8*516)               // sh_x  [8][128]
#define MID_BS   (2*8*516 + 8*128)       // Bs    [2][16][132]
#define MID_RED  (MID_BS + 2*16*132)     // red   [256]
#define MID_D    (MID_RED + 256)         // sh_d  [8]
#define MID_SMEM ((MID_D + 8)*4)

typedef unsigned long long ull;
typedef unsigned int uint;

__device__ uint4 g_AhV[BB*KP2/8];
__device__ uint4 g_AlV[BB*KP2/8];
__device__ uint4 g_WhV[(size_t)GG*KP2/8];
__device__ uint4 g_WlV[(size_t)GG*KP2/8];
__device__ float g_h[HH*BB];          // [j][b]
__device__ float g_c[HH*BB];          // [j][b]
__device__ float g_Bc[(HH+DD)*DD];    // [k][n]
__device__ float g_biasI[GG];
__device__ float g_loss[SS];
__device__ float g_msum[SS];

#define g_Ah ((__nv_bfloat16*)g_AhV)
#define g_Al ((__nv_bfloat16*)g_AlV)
#define g_Wh ((__nv_bfloat16*)g_WhV)
#define g_Wl ((__nv_bfloat16*)g_WlV)

__device__ __forceinline__ size_t aoff(int b, int k){
    int ch = k >> 6;
    int u  = ((k >> 3) & 7) ^ (b & 7);
    return (((size_t)ch*BB + b)*8 + u)*8 + (k & 7);
}
__device__ __forceinline__ size_t woff(int g, int k){
    int ch = k >> 6;
    int u  = ((k >> 3) & 7) ^ (g & 7);
    return (((size_t)ch*GG + g)*8 + u)*8 + (k & 7);
}

__device__ __forceinline__ ull pack2(float lo, float hi){
    ull r; asm("mov.b64 %0, {%1,%2};" : "=l"(r) : "f"(lo), "f"(hi)); return r;
}
__device__ __forceinline__ void unpack2(ull v, float &lo, float &hi){
    asm("mov.b64 {%0,%1}, %2;" : "=f"(lo), "=f"(hi) : "l"(v));
}
__device__ __forceinline__ ull ffma2(ull a, ull b, ull c){
    ull d; asm("fma.rn.f32x2 %0, %1, %2, %3;" : "=l"(d) : "l"(a), "l"(b), "l"(c)); return d;
}
__device__ __forceinline__ float fsigmoid(float x){ return __fdividef(1.f, 1.f + __expf(-x)); }
__device__ __forceinline__ float ftanh(float x){
    float r; asm("tanh.approx.f32 %0, %1;" : "=f"(r) : "f"(x)); return r;
}
__device__ __forceinline__ uint smem_u32(const void* p){
    uint a; asm("{ .reg .u64 t; cvta.to.shared.u64 t, %1; cvt.u32.u64 %0, t; }" : "=r"(a) : "l"(p));
    return a;
}
__device__ __forceinline__ void bsplit(float v, __nv_bfloat16 &h, __nv_bfloat16 &l){
    h = __float2bfloat16(v);
    l = __float2bfloat16(v - __bfloat162float(h));
}
__device__ __forceinline__ void cp16(uint dst, const void* src){
    asm volatile("cp.async.cg.shared.global [%0], [%1], 16;" :: "r"(dst), "l"(src));
}
#define CP_COMMIT() asm volatile("cp.async.commit_group;" ::: "memory")
#define CP_WAIT1()  asm volatile("cp.async.wait_group 1;" ::: "memory")
#define CP_WAIT0()  asm volatile("cp.async.wait_group 0;" ::: "memory")

#define MBAR_INIT(a) asm volatile("mbarrier.init.shared.b64 [%0], %1;" :: "r"(a), "r"(1u) : "memory")
#define MBAR_EXPECT(a, bytes) asm volatile("mbarrier.arrive.expect_tx.shared.b64 _, [%0], %1;" :: "r"(a), "r"(bytes) : "memory")
#define WAITP(a, par) do{ \
    asm volatile("{\n\t.reg .pred P;\n\tWL_%=:\n\t" \
      "mbarrier.try_wait.parity.acquire.cta.shared::cta.b64 P, [%0], %1, 0x989680;\n\t" \
      "@P bra.uni WD_%=;\n\tbra.uni WL_%=;\n\tWD_%=:\n\t}" \
      :: "r"(a), "r"(par) : "memory"); }while(0)
#define BULK_G2S(dst, src, bytes, mbar) \
    asm volatile("cp.async.bulk.shared::cluster.global.mbarrier::complete_tx::bytes [%0], [%1], %2, [%3];" \
        :: "r"(dst), "l"(src), "r"(bytes), "r"(mbar) : "memory")

__device__ __forceinline__ void mma16816(float* c, const uint* a, uint b0, uint b1){
    asm volatile("mma.sync.aligned.m16n8k16.row.col.f32.bf16.bf16.f32 "
        "{%0,%1,%2,%3}, {%4,%5,%6,%7}, {%8,%9}, {%0,%1,%2,%3};"
        : "+f"(c[0]), "+f"(c[1]), "+f"(c[2]), "+f"(c[3])
        : "r"(a[0]), "r"(a[1]), "r"(a[2]), "r"(a[3]), "r"(b0), "r"(b1));
}
#define LDM4(r, addr) \
    asm volatile("ldmatrix.sync.aligned.m8n8.x4.shared.b16 {%0,%1,%2,%3}, [%4];" \
        : "=r"((r)[0]), "=r"((r)[1]), "=r"((r)[2]), "=r"((r)[3]) : "r"(addr))

// ---------------- init ----------------
__global__ void init_kernel(const float* __restrict__ data, const float* __restrict__ masks,
                            const float* __restrict__ deltas, const float* __restrict__ bhr){
    int t = blockIdx.x*blockDim.x + threadIdx.x;
    int stride = gridDim.x*blockDim.x;
    for (int idx=t; idx<BB*KP2; idx+=stride){
        int b = idx/KP2, k = idx - b*KP2;
        float v = 0.f;
        if (k < DD){
            float m = masks[(size_t)b*SS*DD + k];
            v = m*data[(size_t)b*SS*DD + k] + (1.f-m)*bhr[k];
        } else if (k >= DD+HH && k < 2*DD+HH){
            v = masks[(size_t)b*SS*DD + (k-DD-HH)];
        } else if (k == 2*DD+HH){
            v = deltas[(size_t)b*SS];
        }
        __nv_bfloat16 h, l; bsplit(v, h, l);
        size_t o = aoff(b, k);
        g_Ah[o] = h; g_Al[o] = l;
    }
    for (int i=t;i<HH*BB;i+=stride) g_c[i]=0.f;
    if (t < SS) g_loss[t]=0.f;
}

// ---------------- build ----------------
__global__ void build_kernel(const float* __restrict__ Wih, const float* __restrict__ Whh,
                             const float* __restrict__ bih, const float* __restrict__ bhh,
                             const float* __restrict__ Whr, const float* __restrict__ Wfr){
    int t0 = blockIdx.x*blockDim.x + threadIdx.x;
    int stride = gridDim.x*blockDim.x;
    const int IN = 2*DD + 1;
    for (size_t idx=t0; idx<(size_t)GG*KP2; idx+=stride){
        int gcol = (int)(idx / KP2);
        int k    = (int)(idx - (size_t)gcol*KP2);
        int j = gcol >> 2, gate = gcol & 3;
        int gs = gate*HH + j;
        float v = 0.f;
        if (k < DD)            v = Wih[(size_t)gs*IN + k];
        else if (k < DD+HH)    v = Whh[(size_t)gs*HH + (k-DD)];
        else if (k < 2*DD+HH)  v = Wih[(size_t)gs*IN + DD + (k-DD-HH)];
        else if (k == 2*DD+HH) v = Wih[(size_t)gs*IN + 2*DD];
        __nv_bfloat16 h, l; bsplit(v, h, l);
        size_t o = woff(gcol, k);
        g_Wh[o] = h; g_Wl[o] = l;
    }
    for (int gcol=t0; gcol<GG; gcol+=stride){
        int j = gcol>>2, gate = gcol&3; int gs = gate*HH + j;
        g_biasI[gcol] = bih[gs] + bhh[gs];
    }
    for (int idx=t0; idx<(HH+DD)*DD; idx+=stride){
        int k = idx >> 7, n = idx & (DD-1);
        g_Bc[idx] = (k < HH) ? Whr[(size_t)n*HH + k] : Wfr[(size_t)n*DD + (k-HH)];
    }
}

__global__ void msum_kernel(const float* __restrict__ masks){
    __shared__ float red[256];
    int s = blockIdx.x;
    float sum = 0.f;
    for (int idx = threadIdx.x; idx < BB*DD; idx += 256){
        int b = idx >> 7, d = idx & (DD-1);
        sum += masks[(size_t)b*SS*DD + (size_t)s*DD + d];
    }
    red[threadIdx.x] = sum; __syncthreads();
    #pragma unroll
    for (int off=128; off>0; off>>=1){
        if (threadIdx.x < off) red[threadIdx.x] += red[threadIdx.x+off];
        __syncthreads();
    }
    if (threadIdx.x == 0) g_msum[s] = red[0];
}

// ---------------- gates ----------------
__global__ __launch_bounds__(512,1) void gates_kernel(){
    extern __shared__ __align__(16) char smem[];
    uint sb = smem_u32(smem);
    uint mb0 = sb + 2*BUF_B;
    uint mb1 = mb0 + 8;
    int tid = threadIdx.x;
    int w    = tid >> 5;
    int lane = tid & 31;
    int g  = lane >> 2;
    int t2 = lane & 3;
    int wm = w & 3;
    int wn = w >> 2;
    int row0 = blockIdx.y * 128;
    int col0 = blockIdx.x * 128;

    if (tid == 0){ MBAR_INIT(mb0); MBAR_INIT(mb1); }
    __syncthreads();

    int lrow = lane & 15;
    int hi   = lane >> 4;
    int sw7  = lrow & 7;
    uint baseA0 = (uint)((wm*32 +      lrow)*128);
    uint baseA1 = (uint)((wm*32 + 16 + lrow)*128);
    uint baseB0 = (uint)((wn*32 +      lrow)*128);
    uint baseB1 = (uint)((wn*32 + 16 + lrow)*128);

    float acc[32];
    #pragma unroll
    for (int i = 0; i < 32; i++) acc[i] = 0.f;

    if (tid == 0){
        MBAR_EXPECT(mb0, 4*TILE16K);
        BULK_G2S(sb + 0*TILE16K, g_Ah + ((size_t)0*BB + row0)*64, TILE16K, mb0);
        BULK_G2S(sb + 1*TILE16K, g_Al + ((size_t)0*BB + row0)*64, TILE16K, mb0);
        BULK_G2S(sb + 2*TILE16K, g_Wh + ((size_t)0*GG + col0)*64, TILE16K, mb0);
        BULK_G2S(sb + 3*TILE16K, g_Wl + ((size_t)0*GG + col0)*64, TILE16K, mb0);
    }

    uint fah[2][2][4], fal[2][2][4], fbh[2][2][4], fbl[2][2][4];

    uint ph0 = 0, ph1 = 0;
    for (int ch = 0; ch < NCH; ch++){
        int buf = ch & 1;
        uint mb = buf ? mb1 : mb0;
        if (buf){ WAITP(mb, ph1); ph1 ^= 1; }
        else    { WAITP(mb, ph0); ph0 ^= 1; }

        if (tid == 0 && ch+1 < NCH){
            int nb = (ch+1) & 1;
            uint mbn = nb ? mb1 : mb0;
            uint db = sb + nb*BUF_B;
            size_t kcA = ((size_t)(ch+1)*BB + row0)*64;
            size_t kcW = ((size_t)(ch+1)*GG + col0)*64;
            MBAR_EXPECT(mbn, 4*TILE16K);
            BULK_G2S(db + 0*TILE16K, g_Ah + kcA, TILE16K, mbn);
            BULK_G2S(db + 1*TILE16K, g_Al + kcA, TILE16K, mbn);
            BULK_G2S(db + 2*TILE16K, g_Wh + kcW, TILE16K, mbn);
            BULK_G2S(db + 3*TILE16K, g_Wl + kcW, TILE16K, mbn);
        }

        uint tAh = sb + buf*BUF_B;
        uint tAl = tAh + TILE16K;
        uint tBh = tAh + 2*TILE16K;
        uint tBl = tAh + 3*TILE16K;

        {
            uint off = (uint)((((0<<1)|hi) ^ sw7) << 4);
            LDM4(fah[0][0], tAh + baseA0 + off); LDM4(fah[0][1], tAh + baseA1 + off);
            LDM4(fal[0][0], tAl + baseA0 + off); LDM4(fal[0][1], tAl + baseA1 + off);
            LDM4(fbh[0][0], tBh + baseB0 + off); LDM4(fbh[0][1], tBh + baseB1 + off);
            LDM4(fbl[0][0], tBl + baseB0 + off); LDM4(fbl[0][1], tBl + baseB1 + off);
        }
        #pragma unroll
        for (int kk = 0; kk < 4; kk++){
            int cur = kk & 1, nxt = cur ^ 1;
            if (kk < 3){
                uint off = (uint)(((((kk+1)<<1)|hi) ^ sw7) << 4);
                LDM4(fah[nxt][0], tAh + baseA0 + off); LDM4(fah[nxt][1], tAh + baseA1 + off);
                LDM4(fal[nxt][0], tAl + baseA0 + off); LDM4(fal[nxt][1], tAl + baseA1 + off);
                LDM4(fbh[nxt][0], tBh + baseB0 + off); LDM4(fbh[nxt][1], tBh + baseB1 + off);
                LDM4(fbl[nxt][0], tBl + baseB0 + off); LDM4(fbl[nxt][1], tBl + baseB1 + off);
            }
            #pragma unroll
            for (int ma = 0; ma < 2; ma++)
                #pragma unroll
                for (int na = 0; na < 4; na++){
                    int nb = na >> 1, hf = na & 1;
                    mma16816(&acc[(ma*4+na)*4], fah[cur][ma], fbh[cur][nb][hf], fbh[cur][nb][hf+2]);
                }
            #pragma unroll
            for (int ma = 0; ma < 2; ma++)
                #pragma unroll
                for (int na = 0; na < 4; na++){
                    int nb = na >> 1, hf = na & 1;
                    mma16816(&acc[(ma*4+na)*4], fah[cur][ma], fbl[cur][nb][hf], fbl[cur][nb][hf+2]);
                }
            #pragma unroll
            for (int ma = 0; ma < 2; ma++)
                #pragma unroll
                for (int na = 0; na < 4; na++){
                    int nb = na >> 1, hf = na & 1;
                    mma16816(&acc[(ma*4+na)*4], fal[cur][ma], fbh[cur][nb][hf], fbh[cur][nb][hf+2]);
                }
        }
        __syncthreads();
    }

    // fused LSTM epilogue (fast math)
    #pragma unroll
    for (int ma = 0; ma < 2; ma++){
        #pragma unroll
        for (int na = 0; na < 4; na++){
            float* c = &acc[(ma*4 + na)*4];
            int nb = col0 + wn*32 + na*8;
            int gc = nb + t2*2;
            float2 bi = *(const float2*)&g_biasI[gc];
            c[0] += bi.x; c[1] += bi.y; c[2] += bi.x; c[3] += bi.y;
            float p0 = __shfl_xor_sync(0xFFFFFFFFu, c[0], 1);
            float p1 = __shfl_xor_sync(0xFFFFFFFFu, c[1], 1);
            float p2 = __shfl_xor_sync(0xFFFFFFFFu, c[2], 1);
            float p3 = __shfl_xor_sync(0xFFFFFFFFu, c[3], 1);
            int j = (nb >> 2) + (t2 >> 1);
            int row = wm*32 + ma*16 + g + ((t2 & 1) ? 8 : 0);
            float gi, gf, gg, go;
            if ((t2 & 1) == 0){ gi = c[0]; gf = c[1]; gg = p0; go = p1; }
            else              { gi = p2;   gf = p3;   gg = c[2]; go = c[3]; }
            int b = row0 + row;
            size_t o = (size_t)j*BB + b;
            float cold = g_c[o];
            float cn = fsigmoid(gf)*cold + fsigmoid(gi)*ftanh(gg);
            g_c[o] = cn;
            g_h[o] = fsigmoid(go)*ftanh(cn);
        }
    }
}

// ---------------- mid: stepC(s) + prepA(s+1) fused, dyn smem ----------------
__global__ __launch_bounds__(256,1) void mid_kernel(
    const float* __restrict__ data, const float* __restrict__ masks,
    const float* __restrict__ deltas, const float* __restrict__ Wtd,
    const float* __restrict__ btd, const float* __restrict__ bhr,
    const float* __restrict__ bfr, float* __restrict__ out, int s)
{
    extern __shared__ __align__(16) float smd[];
    float* sh_h  = smd + MID_H;     // [8][516]
    float* sh_hd = smd + MID_HD;    // [8][516]
    float* sh_x  = smd + MID_X;     // [8][128]
    float* Bsb   = smd + MID_BS;    // [2][16][132]
    float* red   = smd + MID_RED;   // [256]
    float* sh_d  = smd + MID_D;     // [8]
    int tid = threadIdx.x;
    int m0 = blockIdx.x * 8;
    int tx = tid & 31, ty = tid >> 5;
    bool hasNext = (s+1 < SS);

    int st_kk = tid >> 5;
    int st_n4 = (tid & 31) << 2;
    uint bsaddr0 = smem_u32(Bsb);
    uint bsrow  = (uint)(st_kk*132 + st_n4)*4;
    uint bsrow2 = (uint)((st_kk+8)*132 + st_n4)*4;
    #define STAGE(k0, bu) do{ \
        cp16(bsaddr0 + (bu)*16*132*4 + bsrow,  &g_Bc[(size_t)((k0)+st_kk)*DD + st_n4]); \
        cp16(bsaddr0 + (bu)*16*132*4 + bsrow2, &g_Bc[(size_t)((k0)+st_kk+8)*DD + st_n4]); \
        CP_COMMIT(); }while(0)

    STAGE(0, 0);

    if (tid < 8) sh_d[tid] = hasNext ? deltas[(size_t)(m0+tid)*SS + s + 1] : 0.f;
    __syncthreads();

    #pragma unroll 4
    for (int i = 0; i < 16; i++){
        int lin = i*256 + tid;
        int k = lin >> 3, r = lin & 7;
        float hv = g_h[(size_t)k*BB + m0 + r];
        sh_h[r*516 + k] = hv;
        float hd = 0.f;
        if (hasNext){
            float td = sh_d[r]*Wtd[k] + btd[k];
            hd = hv * __expf(-fmaxf(td, 0.f));
        }
        sh_hd[r*516 + k] = hd;
    }
    {
        int r = tid >> 5, n4 = (tid & 31) << 2;
        *(float4*)&sh_x[r*128 + n4] = *(const float4*)&data[((size_t)(m0+r)*SS + s)*DD + n4];
    }
    __syncthreads();

    if (hasNext){
        int r = tid >> 5, lw = tid & 31;
        int b = m0 + r;
        __align__(16) __nv_bfloat16 th[16], tl[16];
        #pragma unroll
        for (int q = 0; q < 16; q++) bsplit(sh_hd[r*516 + lw*16+q], th[q], tl[q]);
        #pragma unroll
        for (int h2 = 0; h2 < 2; h2++){
            int ug = 16 + lw*2 + h2;
            int ch = ug >> 3, u = (ug & 7) ^ (b & 7);
            size_t o = (((size_t)ch*BB + b)*8 + u)*8;
            *(uint4*)(g_Ah + o) = *(uint4*)(th + h2*8);
            *(uint4*)(g_Al + o) = *(uint4*)(tl + h2*8);
        }
    }

    ull aH[2]={0,0}, aD[2]={0,0}, aX[2]={0,0};
    for (int k0 = 0; k0 < HH+DD; k0 += 16){
        int buf = (k0 >> 4) & 1;
        if (k0 + 16 < HH+DD){ STAGE(k0+16, buf^1); CP_WAIT1(); }
        else CP_WAIT0();
        __syncthreads();
        const float* Bt = Bsb + buf*16*132;
        if (k0 < HH){
            #pragma unroll
            for (int kk = 0; kk < 16; kk++){
                float4 bv = *(const float4*)&Bt[kk*132 + tx*4];
                ull b0 = pack2(bv.x, bv.y), b1 = pack2(bv.z, bv.w);
                float ah = sh_h[ty*516 + k0+kk];  ull a2 = pack2(ah, ah);
                aH[0] = ffma2(a2, b0, aH[0]); aH[1] = ffma2(a2, b1, aH[1]);
                float ad = sh_hd[ty*516 + k0+kk]; ull d2 = pack2(ad, ad);
                aD[0] = ffma2(d2, b0, aD[0]); aD[1] = ffma2(d2, b1, aD[1]);
            }
        } else {
            #pragma unroll
            for (int kk = 0; kk < 16; kk++){
                float4 bv = *(const float4*)&Bt[kk*132 + tx*4];
                float ax = sh_x[ty*128 + k0-HH+kk]; ull a2 = pack2(ax, ax);
                aX[0] = ffma2(a2, pack2(bv.x,bv.y), aX[0]);
                aX[1] = ffma2(a2, pack2(bv.z,bv.w), aX[1]);
            }
        }
        __syncthreads();
    }

    int b = m0 + ty, n0 = tx*4;
    float h2v[4], xf[4], hd[4];
    unpack2(aH[0], h2v[0], h2v[1]); unpack2(aH[1], h2v[2], h2v[3]);
    unpack2(aX[0], xf[0], xf[1]);  unpack2(aX[1], xf[2], xf[3]);
    unpack2(aD[0], hd[0], hd[1]);  unpack2(aD[1], hd[2], hd[3]);
    float4 brv = *(const float4*)&bhr[n0];
    float4 frv = *(const float4*)&bfr[n0];
    float4 xv  = *(const float4*)&data [((size_t)b*SS + s)*DD + n0];
    float4 mv  = *(const float4*)&masks[((size_t)b*SS + s)*DD + n0];
    float brr[4]={brv.x,brv.y,brv.z,brv.w}, frr[4]={frv.x,frv.y,frv.z,frv.w};
    float xr[4]={xv.x,xv.y,xv.z,xv.w},      mr[4]={mv.x,mv.y,mv.z,mv.w};
    float lsum = 0.f, ov[4];
    #pragma unroll
    for (int q = 0; q < 4; q++){
        float xh2 = h2v[q] + brr[q];
        float xff = xf[q] + frr[q];
        ov[q] = mr[q]*xr[q] + (1.f-mr[q])*(xh2 + xff);
        float e = xr[q] - xh2;
        lsum += e*e*mr[q];
    }
    *(float4*)&out[((size_t)b*SS + s)*DD + n0] = make_float4(ov[0], ov[1], ov[2], ov[3]);

    if (hasNext){
        float4 xn = *(const float4*)&data [((size_t)b*SS + s+1)*DD + n0];
        float4 mn = *(const float4*)&masks[((size_t)b*SS + s+1)*DD + n0];
        float xnr[4]={xn.x,xn.y,xn.z,xn.w}, mnr[4]={mn.x,mn.y,mn.z,mn.w};
        __align__(8) __nv_bfloat16 ah4[4], al4[4], mh4[4], ml4[4];
        #pragma unroll
        for (int q = 0; q < 4; q++){
            float xh = hd[q] + brr[q];
            float xc = mnr[q]*xnr[q] + (1.f-mnr[q])*xh;
            bsplit(xc, ah4[q], al4[q]);
            bsplit(mnr[q], mh4[q], ml4[q]);
        }
        {
            int ug = n0 >> 3;
            int ch = ug >> 3, u = (ug & 7) ^ (b & 7);
            size_t o = (((size_t)ch*BB + b)*8 + u)*8 + (n0 & 7);
            *(uint2*)(g_Ah + o) = *(uint2*)ah4;
            *(uint2*)(g_Al + o) = *(uint2*)al4;
        }
        {
            int ug = 80 + (n0 >> 3);
            int ch = ug >> 3, u = (ug & 7) ^ (b & 7);
            size_t o = (((size_t)ch*BB + b)*8 + u)*8 + (n0 & 7);
            *(uint2*)(g_Ah + o) = *(uint2*)mh4;
            *(uint2*)(g_Al + o) = *(uint2*)ml4;
        }
        if (tx == 0){
            __nv_bfloat16 dh, dl; bsplit(sh_d[ty], dh, dl);
            size_t o = (((size_t)12*BB + b)*8 + (b & 7))*8;
            g_Ah[o] = dh;
            g_Al[o] = dl;
        }
    }

    red[tid] = lsum; __syncthreads();
    #pragma unroll
    for (int off = 128; off > 0; off >>= 1){
        if (tid < off) red[tid] += red[tid+off];
        __syncthreads();
    }
    if (tid == 0) atomicAdd(&g_loss[s], red[0]);
}

__global__ void final_kernel(float* __restrict__ out, int out_size){
    __shared__ float red[256];
    int s = threadIdx.x;
    red[s] = g_loss[s] / (g_msum[s] + 1e-5f);
    __syncthreads();
    #pragma unroll
    for (int off = 128; off > 0; off >>= 1){
        if (s < off) red[s] += red[s+off];
        __syncthreads();
    }
    if (s == 0 && out_size > NIMP) out[NIMP] = red[0] / (float)SS;
}

extern "C" void kernel_launch(void* const* d_in, const int* in_sizes, int n_in,
                              void* d_out, int out_size){
    const float* data   = (const float*)d_in[0];
    const float* masks  = (const float*)d_in[1];
    const float* deltas = (const float*)d_in[2];
    const float* Wih    = (const float*)d_in[3];
    const float* Whh    = (const float*)d_in[4];
    const float* bih    = (const float*)d_in[5];
    const float* bhh    = (const float*)d_in[6];
    const float* Wtd    = (const float*)d_in[7];
    const float* btd    = (const float*)d_in[8];
    const float* Whr    = (const float*)d_in[9];
    const float* bhr    = (const float*)d_in[10];
    const float* Wfr    = (const float*)d_in[11];
    const float* bfr    = (const float*)d_in[12];
    float* out = (float*)d_out;

    cudaFuncSetAttribute(gates_kernel, cudaFuncAttributeMaxDynamicSharedMemorySize, GATES_SMEM);
    cudaFuncSetAttribute(mid_kernel, cudaFuncAttributeMaxDynamicSharedMemorySize, MID_SMEM);

    init_kernel<<<512, 256>>>(data, masks, deltas, bhr);
    build_kernel<<<512, 256>>>(Wih, Whh, bih, bhh, Whr, Wfr);
    msum_kernel<<<SS, 256>>>(masks);
    for (int s = 0; s < SS; s++){
        gates_kernel<<<dim3(16, 8), 512, GATES_SMEM>>>();
        mid_kernel<<<BB/8, 256, MID_SMEM>>>(data, masks, deltas, Wtd, btd, bhr, bfr, out, s);
    }
    final_kernel<<<1, 256>>>(out, out_size);
}